// round 2
// baseline (speedup 1.0000x reference)
#include <cuda_runtime.h>

#define DDIM 256
#define MT 64           // rows per block tile
#define KT 128          // codes per k-chunk
#define DC 16           // depth per inner chunk
#define NBLK 1024       // 65536/64

__device__ float g_cnorm[1024];
__device__ float g_partial[NBLK];

// packed dual-FMA: d.lo += a.lo*b.lo, d.hi += a.hi*b.hi  (exact fp32 lanes)
#define FFMA2(d, a, b) asm("fma.rn.f32x2 %0, %1, %2, %0;" : "+l"(d) : "l"(a), "l"(b))

// ws: transposed [d][k], swizzle in 4-word units (same as R1, conflict-free)
__device__ __forceinline__ int swW(int d, int k) {
    return d * KT + (k ^ (((d >> 2) & 7) << 2));
}
// zs: transposed + duplicated [d][2m,2m+1]={z,z}, swizzle in 4-word units
__device__ __forceinline__ int swZ(int d, int m2) {   // m2 = 2*m
    return d * (2 * MT) + (m2 ^ ((d & 7) << 2));
}

__global__ void cnorm_kernel(const float* __restrict__ w, int K) {
    int k = blockIdx.x * 8 + (threadIdx.x >> 5);
    int lane = threadIdx.x & 31;
    if (k >= K) return;
    const float4* wr = (const float4*)(w + (size_t)k * DDIM);
    float4 v0 = wr[lane];
    float4 v1 = wr[lane + 32];
    float s = v0.x*v0.x + v0.y*v0.y + v0.z*v0.z + v0.w*v0.w
            + v1.x*v1.x + v1.y*v1.y + v1.z*v1.z + v1.w*v1.w;
    #pragma unroll
    for (int m = 16; m; m >>= 1) s += __shfl_xor_sync(0xffffffffu, s, m);
    if (lane == 0) g_cnorm[k] = s;
}

__global__ void __launch_bounds__(256, 3)
vq_kernel(const float* __restrict__ z, const float* __restrict__ w,
          float* __restrict__ out, int N, int K)
{
    __shared__ __align__(16) float zs[DC * 2 * MT];   // 8 KB (duplicated)
    __shared__ __align__(16) float ws[DC * KT];       // 8 KB
    __shared__ float s_minval[MT];
    __shared__ int   s_minidx[MT];
    __shared__ float s_cn[KT];
    __shared__ float s_red[256];

    const int tid = threadIdx.x;
    const int tx = tid & 15;
    const int ty = tid >> 4;
    const int rowBase = blockIdx.x * MT;

    if (tid < MT) { s_minval[tid] = 3.4e38f; s_minidx[tid] = 0; }

    const int m0 = ty * 4;          // 4 fragment rows
    const int c0 = tx * 4;          // fragment code groups
    const int c1 = 64 + tx * 4;

    const int frow = tid >> 2;      // fill indices (z tile: 64 rows x 4 float4)
    const int fc4  = tid & 3;
    const int fdb  = fc4 * 4;

    for (int kc = 0; kc < K; kc += KT) {
        unsigned long long acc[4][4];   // [row][code-pair], packed f32x2
        #pragma unroll
        for (int i = 0; i < 4; i++)
            #pragma unroll
            for (int j = 0; j < 4; j++) acc[i][j] = 0ull;

        if (tid < KT) s_cn[tid] = g_cnorm[kc + tid];

        for (int dc = 0; dc < DDIM; dc += DC) {
            // ---- fill: z (duplicated pairs, 1 pass) + w (2 passes) ----
            {
                float4 v = *(const float4*)(z + (size_t)(rowBase + frow) * DDIM + dc + fc4 * 4);
                *(float2*)&zs[swZ(fdb + 0, 2 * frow)] = make_float2(v.x, v.x);
                *(float2*)&zs[swZ(fdb + 1, 2 * frow)] = make_float2(v.y, v.y);
                *(float2*)&zs[swZ(fdb + 2, 2 * frow)] = make_float2(v.z, v.z);
                *(float2*)&zs[swZ(fdb + 3, 2 * frow)] = make_float2(v.w, v.w);
            }
            #pragma unroll
            for (int it = 0; it < 2; it++) {
                int q   = tid + 256 * it;
                int row = q >> 2;
                int c4  = q & 3;
                int db  = c4 * 4;
                float4 u = *(const float4*)(w + (size_t)(kc + row) * DDIM + dc + c4 * 4);
                ws[swW(db + 0, row)] = u.x;
                ws[swW(db + 1, row)] = u.y;
                ws[swW(db + 2, row)] = u.z;
                ws[swW(db + 3, row)] = u.w;
            }
            __syncthreads();

            // ---- packed-FMA inner loop: 16 fma.f32x2 per d ----
            #pragma unroll
            for (int d = 0; d < DC; d++) {
                ulonglong2 A0 = *(const ulonglong2*)&zs[swZ(d, 2 * m0)];       // dup(m0),dup(m0+1)
                ulonglong2 A1 = *(const ulonglong2*)&zs[swZ(d, 2 * m0 + 4)];   // dup(m0+2),dup(m0+3)
                ulonglong2 B0 = *(const ulonglong2*)&ws[swW(d, c0)];           // (c0,c0+1),(c0+2,c0+3)
                ulonglong2 B1 = *(const ulonglong2*)&ws[swW(d, c1)];
                unsigned long long a[4] = {A0.x, A0.y, A1.x, A1.y};
                unsigned long long b[4] = {B0.x, B0.y, B1.x, B1.y};
                #pragma unroll
                for (int i = 0; i < 4; i++) {
                    #pragma unroll
                    for (int j = 0; j < 4; j++)
                        FFMA2(acc[i][j], a[i], b[j]);
                }
            }
            __syncthreads();
        }

        // ---- scoring: s = ||e||^2 - 2*dot, ascending-code argmin ----
        #pragma unroll
        for (int i = 0; i < 4; i++) {
            float bv = 3.4e38f;
            int   bi = 0x7fffffff;
            #pragma unroll
            for (int jp = 0; jp < 4; jp++) {
                int cl = (jp < 2) ? (c0 + 2 * jp) : (c1 + 2 * (jp - 2));
                unsigned long long v = acc[i][jp];
                float lo = __uint_as_float((unsigned)(v & 0xffffffffu));
                float hi = __uint_as_float((unsigned)(v >> 32));
                float slo = fmaf(-2.f, lo, s_cn[cl]);
                float shi = fmaf(-2.f, hi, s_cn[cl + 1]);
                if (slo < bv) { bv = slo; bi = kc + cl; }
                if (shi < bv) { bv = shi; bi = kc + cl + 1; }
            }
            #pragma unroll
            for (int md = 8; md; md >>= 1) {
                float ov = __shfl_xor_sync(0xffffffffu, bv, md, 16);
                int   oi = __shfl_xor_sync(0xffffffffu, bi, md, 16);
                if (ov < bv || (ov == bv && oi < bi)) { bv = ov; bi = oi; }
            }
            if (tx == 0) {
                int row = m0 + i;
                if (bv < s_minval[row] || (bv == s_minval[row] && bi < s_minidx[row])) {
                    s_minval[row] = bv;
                    s_minidx[row] = bi;
                }
            }
        }
        __syncthreads();   // protect s_cn / s_minval before next chunk
    }

    // ---- epilogue: z_q, indices, loss partial ----
    float* out_zq  = out + 1;
    float* out_idx = out + 1 + (size_t)N * DDIM;

    int row  = tid >> 2;
    int q    = tid & 3;
    int gRow = rowBase + row;
    int idx  = s_minidx[row];
    if (q == 0) out_idx[gRow] = (float)idx;

    const float* wr   = w + (size_t)idx  * DDIM + q * 64;
    const float* zr   = z + (size_t)gRow * DDIM + q * 64;
    float*       orow = out_zq + (size_t)gRow * DDIM + q * 64;

    float lsum = 0.f;
    #pragma unroll 4
    for (int v = 0; v < 16; v++) {
        float4 wv = *(const float4*)(wr + v * 4);
        float4 zv = *(const float4*)(zr + v * 4);
        float d0 = wv.x - zv.x, d1 = wv.y - zv.y, d2 = wv.z - zv.z, d3 = wv.w - zv.w;
        lsum += d0*d0 + d1*d1 + d2*d2 + d3*d3;
        // out+1 base is not 16B aligned -> scalar stores
        orow[v*4 + 0] = wv.x;
        orow[v*4 + 1] = wv.y;
        orow[v*4 + 2] = wv.z;
        orow[v*4 + 3] = wv.w;
    }

    s_red[tid] = lsum;
    __syncthreads();
    #pragma unroll
    for (int m = 128; m; m >>= 1) {
        if (tid < m) s_red[tid] += s_red[tid + m];
        __syncthreads();
    }
    if (tid == 0) g_partial[blockIdx.x] = s_red[0];
}

__global__ void finalize_kernel(float* __restrict__ out, int nblocks, float scale) {
    __shared__ float s[512];
    int t = threadIdx.x;
    float v = 0.f;
    for (int i = t; i < nblocks; i += 512) v += g_partial[i];
    s[t] = v;
    __syncthreads();
    #pragma unroll
    for (int m = 256; m; m >>= 1) {
        if (t < m) s[t] += s[t + m];
        __syncthreads();
    }
    if (t == 0) out[0] = s[0] * scale;
}

extern "C" void kernel_launch(void* const* d_in, const int* in_sizes, int n_in,
                              void* d_out, int out_size) {
    const float* z = (const float*)d_in[0];
    const float* w = (const float*)d_in[1];
    float* out = (float*)d_out;

    int N = in_sizes[0] / DDIM;   // 65536
    int K = in_sizes[1] / DDIM;   // 1024

    cnorm_kernel<<<(K + 7) / 8, 256>>>(w, K);
    vq_kernel<<<N / MT, 256>>>(z, w, out, N, K);
    // loss = BETA * mean((z_q - z)^2), BETA = 0.25
    float scale = 0.25f / ((float)N * (float)DDIM);
    finalize_kernel<<<1, 512>>>(out, N / MT, scale);
}

// round 3
// speedup vs baseline: 1.1815x; 1.1815x over previous
#include <cuda_runtime.h>
#include <cuda_bf16.h>

#define DDIM 256
#define KSPL 768                 // split-K: [hi | lo | hi] for z, [hi | hi | lo] for w
#define NROWS 65536
#define KCODES 1024
#define BM 128
#define BN 128
#define BK 32
#define ASTRIDE 40               // padded bf16 stride (conflict-free LDSM)
#define MARGIN 0.08f
#define INFV 3.4e38f
#define OUTBLK 1024              // 65536/64

__device__ __nv_bfloat16 g_zs[(size_t)NROWS * KSPL];   // 100.7 MB (.bss)
__device__ __nv_bfloat16 g_ws[(size_t)KCODES * KSPL];
__device__ float g_cnorm[KCODES];
__device__ int   g_idx[NROWS];
__device__ int   g_flaglist[NROWS];
__device__ int   g_flagcount;
__device__ float g_partial[OUTBLK];

// ---------------- prep ----------------
__global__ void split_z_kernel(const float* __restrict__ z) {
    int e4 = blockIdx.x * blockDim.x + threadIdx.x;     // float4 index
    int base = e4 * 4;
    int row = base >> 8;
    int d   = base & 255;
    float4 v = *(const float4*)(z + base);
    __nv_bfloat16 h[4], l[4];
    float vv[4] = {v.x, v.y, v.z, v.w};
    #pragma unroll
    for (int i = 0; i < 4; i++) {
        h[i] = __float2bfloat16_rn(vv[i]);
        l[i] = __float2bfloat16_rn(vv[i] - __bfloat162float(h[i]));
    }
    __nv_bfloat162 hp0 = {h[0], h[1]}, hp1 = {h[2], h[3]};
    __nv_bfloat162 lp0 = {l[0], l[1]}, lp1 = {l[2], l[3]};
    __nv_bfloat162* p0 = (__nv_bfloat162*)&g_zs[(size_t)row * KSPL + d];
    p0[0] = hp0; p0[1] = hp1;
    __nv_bfloat162* p1 = (__nv_bfloat162*)&g_zs[(size_t)row * KSPL + 256 + d];
    p1[0] = lp0; p1[1] = lp1;
    __nv_bfloat162* p2 = (__nv_bfloat162*)&g_zs[(size_t)row * KSPL + 512 + d];
    p2[0] = hp0; p2[1] = hp1;
}

__global__ void split_w_kernel(const float* __restrict__ w) {
    if (blockIdx.x == 0 && threadIdx.x == 0) g_flagcount = 0;
    int e4 = blockIdx.x * blockDim.x + threadIdx.x;
    int base = e4 * 4;
    int row = base >> 8;
    int d   = base & 255;
    float4 v = *(const float4*)(w + base);
    __nv_bfloat16 h[4], l[4];
    float vv[4] = {v.x, v.y, v.z, v.w};
    #pragma unroll
    for (int i = 0; i < 4; i++) {
        h[i] = __float2bfloat16_rn(vv[i]);
        l[i] = __float2bfloat16_rn(vv[i] - __bfloat162float(h[i]));
    }
    __nv_bfloat162 hp0 = {h[0], h[1]}, hp1 = {h[2], h[3]};
    __nv_bfloat162 lp0 = {l[0], l[1]}, lp1 = {l[2], l[3]};
    __nv_bfloat162* p0 = (__nv_bfloat162*)&g_ws[(size_t)row * KSPL + d];
    p0[0] = hp0; p0[1] = hp1;
    __nv_bfloat162* p1 = (__nv_bfloat162*)&g_ws[(size_t)row * KSPL + 256 + d];
    p1[0] = hp0; p1[1] = hp1;
    __nv_bfloat162* p2 = (__nv_bfloat162*)&g_ws[(size_t)row * KSPL + 512 + d];
    p2[0] = lp0; p2[1] = lp1;
}

__global__ void cnorm_kernel(const float* __restrict__ w, int K) {
    int k = blockIdx.x * 8 + (threadIdx.x >> 5);
    int lane = threadIdx.x & 31;
    if (k >= K) return;
    const float4* wr = (const float4*)(w + (size_t)k * DDIM);
    float4 v0 = wr[lane];
    float4 v1 = wr[lane + 32];
    float s = v0.x*v0.x + v0.y*v0.y + v0.z*v0.z + v0.w*v0.w
            + v1.x*v1.x + v1.y*v1.y + v1.z*v1.z + v1.w*v1.w;
    #pragma unroll
    for (int m = 16; m; m >>= 1) s += __shfl_xor_sync(0xffffffffu, s, m);
    if (lane == 0) g_cnorm[k] = s;
}

// ---------------- GEMM helpers ----------------
__device__ __forceinline__ void cp16(unsigned saddr, const void* gaddr) {
    asm volatile("cp.async.cg.shared.global [%0], [%1], 16;\n" :: "r"(saddr), "l"(gaddr) : "memory");
}
__device__ __forceinline__ void cp_commit() { asm volatile("cp.async.commit_group;\n" ::: "memory"); }
template<int N> __device__ __forceinline__ void cp_wait() {
    asm volatile("cp.async.wait_group %0;\n" :: "n"(N) : "memory");
}
__device__ __forceinline__ void ldsm4(unsigned a, unsigned &r0, unsigned &r1, unsigned &r2, unsigned &r3) {
    asm volatile("ldmatrix.sync.aligned.m8n8.x4.shared.b16 {%0,%1,%2,%3}, [%4];"
                 : "=r"(r0), "=r"(r1), "=r"(r2), "=r"(r3) : "r"(a));
}
__device__ __forceinline__ void mma16816(float* c, const unsigned* a, const unsigned* b) {
    asm volatile("mma.sync.aligned.m16n8k16.row.col.f32.bf16.bf16.f32 "
                 "{%0,%1,%2,%3}, {%4,%5,%6,%7}, {%8,%9}, {%0,%1,%2,%3};"
                 : "+f"(c[0]), "+f"(c[1]), "+f"(c[2]), "+f"(c[3])
                 : "r"(a[0]), "r"(a[1]), "r"(a[2]), "r"(a[3]), "r"(b[0]), "r"(b[1]));
}
__device__ __forceinline__ bool lexless(float v, int i, float w, int j) {
    return v < w || (v == w && i < j);
}
__device__ __forceinline__ void top2_merge(float &v1, int &i1, float &v2, int &i2,
                                           float w1, int j1, float w2, int j2) {
    if (lexless(w1, j1, v1, i1)) {
        float nv2; int ni2;
        if (lexless(v1, i1, w2, j2)) { nv2 = v1; ni2 = i1; } else { nv2 = w2; ni2 = j2; }
        v1 = w1; i1 = j1; v2 = nv2; i2 = ni2;
    } else if (lexless(w1, j1, v2, i2)) {
        v2 = w1; i2 = j1;
    }
}

// ---------------- main GEMM + top2 ----------------
__global__ void __launch_bounds__(256, 2)
gemm_kernel(int N, int K)
{
    __shared__ __align__(16) __nv_bfloat16 As[2][BM * ASTRIDE];
    __shared__ __align__(16) __nv_bfloat16 Bs[2][BN * ASTRIDE];
    __shared__ float4 s_part[2][BM];
    __shared__ float4 s_run[BM];
    __shared__ float  s_cn[BN];

    const int tid  = threadIdx.x;
    const int lane = tid & 31;
    const int warp = tid >> 5;
    const int mw   = warp & 3;          // 4 m-warps
    const int nw   = warp >> 2;         // 2 n-warps
    const int wm0  = mw * 32;
    const int wn0  = nw * 64;
    const int rowBase = blockIdx.x * BM;

    unsigned asmem = (unsigned)__cvta_generic_to_shared(&As[0][0]);
    unsigned bsmem = (unsigned)__cvta_generic_to_shared(&Bs[0][0]);
    const unsigned ABYTES = BM * ASTRIDE * 2;

    if (tid < BM) s_run[tid] = make_float4(INFV, __int_as_float(0x7fffffff),
                                           INFV, __int_as_float(0x7fffffff));

    for (int kc = 0; kc < K; kc += BN) {
        if (tid < BN) s_cn[tid] = g_cnorm[kc + tid];

        float acc[2][8][4];
        #pragma unroll
        for (int i = 0; i < 2; i++)
            #pragma unroll
            for (int j = 0; j < 8; j++)
                #pragma unroll
                for (int c = 0; c < 4; c++) acc[i][j][c] = 0.f;

        // prologue: stage 0
        {
            #pragma unroll
            for (int it = 0; it < 2; it++) {
                int c = tid + it * 256;
                int r = c >> 2, s = c & 3;
                cp16(asmem + (unsigned)((r * ASTRIDE + s * 8) * 2),
                     &g_zs[(size_t)(rowBase + r) * KSPL + s * 8]);
                cp16(bsmem + (unsigned)((r * ASTRIDE + s * 8) * 2),
                     &g_ws[(size_t)(kc + r) * KSPL + s * 8]);
            }
            cp_commit();
        }

        const int KS = KSPL / BK;       // 24
        for (int ks = 0; ks < KS; ks++) {
            int buf = ks & 1;
            if (ks + 1 < KS) {
                int nbuf = 1 - buf;
                int kd = (ks + 1) * BK;
                #pragma unroll
                for (int it = 0; it < 2; it++) {
                    int c = tid + it * 256;
                    int r = c >> 2, s = c & 3;
                    cp16(asmem + nbuf * ABYTES + (unsigned)((r * ASTRIDE + s * 8) * 2),
                         &g_zs[(size_t)(rowBase + r) * KSPL + kd + s * 8]);
                    cp16(bsmem + nbuf * ABYTES + (unsigned)((r * ASTRIDE + s * 8) * 2),
                         &g_ws[(size_t)(kc + r) * KSPL + kd + s * 8]);
                }
                cp_commit();
                cp_wait<1>();
            } else {
                cp_wait<0>();
            }
            __syncthreads();

            #pragma unroll
            for (int kk = 0; kk < BK; kk += 16) {
                unsigned a[2][4];
                #pragma unroll
                for (int i = 0; i < 2; i++) {
                    int arow = wm0 + i * 16 + (lane & 15);
                    int acol = kk + ((lane >> 4) << 3);
                    ldsm4(asmem + buf * ABYTES + (unsigned)((arow * ASTRIDE + acol) * 2),
                          a[i][0], a[i][1], a[i][2], a[i][3]);
                }
                unsigned b[8][2];
                #pragma unroll
                for (int p = 0; p < 4; p++) {
                    int brow = wn0 + p * 16 + (lane & 7) + ((lane >> 4) << 3);
                    int bcol = kk + (((lane >> 3) & 1) << 3);
                    ldsm4(bsmem + buf * ABYTES + (unsigned)((brow * ASTRIDE + bcol) * 2),
                          b[2*p][0], b[2*p][1], b[2*p+1][0], b[2*p+1][1]);
                }
                #pragma unroll
                for (int i = 0; i < 2; i++)
                    #pragma unroll
                    for (int j = 0; j < 8; j++)
                        mma16816(acc[i][j], a[i], b[j]);
            }
            __syncthreads();
        }

        // ---- epilogue: per-row top2 over this 128-code chunk ----
        #pragma unroll
        for (int i = 0; i < 2; i++) {
            #pragma unroll
            for (int h = 0; h < 2; h++) {
                float v1 = INFV; int i1 = 0x7fffffff;
                float v2 = INFV; int i2 = 0x7fffffff;
                #pragma unroll
                for (int j = 0; j < 8; j++) {
                    #pragma unroll
                    for (int c = 0; c < 2; c++) {
                        int col = wn0 + j * 8 + (lane & 3) * 2 + c;
                        float val = fmaf(-2.f, acc[i][j][h * 2 + c], s_cn[col]);
                        int idx = kc + col;
                        if (lexless(val, idx, v1, i1)) { v2 = v1; i2 = i1; v1 = val; i1 = idx; }
                        else if (lexless(val, idx, v2, i2)) { v2 = val; i2 = idx; }
                    }
                }
                #pragma unroll
                for (int off = 1; off < 4; off <<= 1) {
                    float ov1 = __shfl_xor_sync(0xffffffffu, v1, off);
                    int   oi1 = __shfl_xor_sync(0xffffffffu, i1, off);
                    float ov2 = __shfl_xor_sync(0xffffffffu, v2, off);
                    int   oi2 = __shfl_xor_sync(0xffffffffu, i2, off);
                    top2_merge(v1, i1, v2, i2, ov1, oi1, ov2, oi2);
                }
                if ((lane & 3) == 0) {
                    int r = wm0 + i * 16 + (lane >> 2) + h * 8;
                    s_part[nw][r] = make_float4(v1, __int_as_float(i1), v2, __int_as_float(i2));
                }
            }
        }
        __syncthreads();
        if (tid < BM) {
            float4 pa = s_part[0][tid];
            float4 pb = s_part[1][tid];
            float v1 = pa.x; int i1 = __float_as_int(pa.y);
            float v2 = pa.z; int i2 = __float_as_int(pa.w);
            top2_merge(v1, i1, v2, i2, pb.x, __float_as_int(pb.y), pb.z, __float_as_int(pb.w));
            float4 r = s_run[tid];
            float r1 = r.x; int ri1 = __float_as_int(r.y);
            float r2 = r.z; int ri2 = __float_as_int(r.w);
            top2_merge(r1, ri1, r2, ri2, v1, i1, v2, i2);
            s_run[tid] = make_float4(r1, __int_as_float(ri1), r2, __int_as_float(ri2));
        }
        __syncthreads();
    }

    if (tid < BM) {
        float4 r = s_run[tid];
        int row = rowBase + tid;
        g_idx[row] = __float_as_int(r.y);
        if (r.z - r.x <= MARGIN) {
            int pos = atomicAdd(&g_flagcount, 1);
            g_flaglist[pos] = row;
        }
    }
}

// ---------------- exact refine of flagged rows ----------------
#define RB 16
__global__ void refine_kernel(const float* __restrict__ z, const float* __restrict__ w, int K) {
    __shared__ float zrows[RB][260];
    __shared__ float wtile[RB][257];
    __shared__ int   rowids[RB];

    const int tid = threadIdx.x;
    const int rr  = tid >> 4;       // row within tile
    const int sub = tid & 15;       // 16 threads per row
    const int fcount = g_flagcount;

    for (int base = blockIdx.x * RB; base < fcount; base += gridDim.x * RB) {
        int cnt = min(RB, fcount - base);
        if (tid < cnt) rowids[tid] = g_flaglist[base + tid];
        __syncthreads();
        for (int e = tid; e < cnt * 256; e += 256)
            zrows[e >> 8][e & 255] = z[(size_t)rowids[e >> 8] * DDIM + (e & 255)];

        float bv = INFV; int bi = 0x7fffffff;
        for (int cb = 0; cb < K; cb += RB) {
            __syncthreads();
            for (int e = tid; e < RB * 256; e += 256)
                wtile[e >> 8][e & 255] = w[(size_t)(cb + (e >> 8)) * DDIM + (e & 255)];
            __syncthreads();
            if (rr < cnt) {
                float dot = 0.f;
                #pragma unroll 8
                for (int d = 0; d < 256; d++)
                    dot = fmaf(zrows[rr][d], wtile[sub][d], dot);
                float val = fmaf(-2.f, dot, g_cnorm[cb + sub]);
                int code = cb + sub;
                if (lexless(val, code, bv, bi)) { bv = val; bi = code; }
            }
        }
        #pragma unroll
        for (int off = 8; off; off >>= 1) {
            float ov = __shfl_xor_sync(0xffffffffu, bv, off, 16);
            int   oi = __shfl_xor_sync(0xffffffffu, bi, off, 16);
            if (lexless(ov, oi, bv, bi)) { bv = ov; bi = oi; }
        }
        if (sub == 0 && rr < cnt) g_idx[rowids[rr]] = bi;
        __syncthreads();
    }
}

// ---------------- output assembly ----------------
__global__ void output_kernel(const float* __restrict__ z, const float* __restrict__ w,
                              float* __restrict__ out, int N)
{
    __shared__ float s_red[256];
    const int tid = threadIdx.x;
    const int rowBase = blockIdx.x * 64;
    int row  = tid >> 2;
    int q    = tid & 3;
    int gRow = rowBase + row;
    int idx  = g_idx[gRow];

    float* out_zq  = out + 1;
    float* out_idx = out + 1 + (size_t)N * DDIM;
    if (q == 0) out_idx[gRow] = (float)idx;

    const float* wr   = w + (size_t)idx  * DDIM + q * 64;
    const float* zr   = z + (size_t)gRow * DDIM + q * 64;
    float*       orow = out_zq + (size_t)gRow * DDIM + q * 64;

    float lsum = 0.f;
    #pragma unroll 4
    for (int v = 0; v < 16; v++) {
        float4 wv = *(const float4*)(wr + v * 4);
        float4 zv = *(const float4*)(zr + v * 4);
        float d0 = wv.x - zv.x, d1 = wv.y - zv.y, d2 = wv.z - zv.z, d3 = wv.w - zv.w;
        lsum += d0*d0 + d1*d1 + d2*d2 + d3*d3;
        orow[v*4 + 0] = wv.x;
        orow[v*4 + 1] = wv.y;
        orow[v*4 + 2] = wv.z;
        orow[v*4 + 3] = wv.w;
    }

    s_red[tid] = lsum;
    __syncthreads();
    #pragma unroll
    for (int m = 128; m; m >>= 1) {
        if (tid < m) s_red[tid] += s_red[tid + m];
        __syncthreads();
    }
    if (tid == 0) g_partial[blockIdx.x] = s_red[0];
}

__global__ void finalize_kernel(float* __restrict__ out, int nblocks, float scale) {
    __shared__ float s[512];
    int t = threadIdx.x;
    float v = 0.f;
    for (int i = t; i < nblocks; i += 512) v += g_partial[i];
    s[t] = v;
    __syncthreads();
    #pragma unroll
    for (int m = 256; m; m >>= 1) {
        if (t < m) s[t] += s[t + m];
        __syncthreads();
    }
    if (t == 0) out[0] = s[0] * scale;
}

extern "C" void kernel_launch(void* const* d_in, const int* in_sizes, int n_in,
                              void* d_out, int out_size) {
    const float* z = (const float*)d_in[0];
    const float* w = (const float*)d_in[1];
    float* out = (float*)d_out;

    int N = in_sizes[0] / DDIM;   // 65536
    int K = in_sizes[1] / DDIM;   // 1024

    split_z_kernel<<<(N * DDIM) / 1024, 256>>>(z);
    split_w_kernel<<<(K * DDIM) / 1024, 256>>>(w);
    cnorm_kernel<<<(K + 7) / 8, 256>>>(w, K);
    gemm_kernel<<<N / BM, 256>>>(N, K);
    refine_kernel<<<64, 256>>>(z, w, K);
    output_kernel<<<N / 64, 256>>>(z, w, out, N);
    float scale = 0.25f / ((float)N * (float)DDIM);
    finalize_kernel<<<1, 512>>>(out, N / 64, scale);
}

// round 5
// speedup vs baseline: 1.6567x; 1.4022x over previous
#include <cuda_runtime.h>
#include <cuda_bf16.h>
#include <cstdint>

#define DDIM 256
#define NROWS 65536
#define KCODES 1024
#define KSPL 512                 // packed [hi(256) | lo(256)]
#define KVIRT 768                // virtual K: zh*wh + zl*wh + zh*wl
#define BM 128
#define BN 128
#define BK 32
#define NSTAGE 3
#define ASTRIDE 40               // padded bf16 stride (conflict-free LDSM)
#define MARGIN 0.05f
#define INFV 3.4e38f
#define OUTRPB 16
#define OUTBLK (NROWS / OUTRPB)  // 4096

__device__ __nv_bfloat16 g_zs[(size_t)NROWS * KSPL];   // 64 MB
__device__ __nv_bfloat16 g_ws[(size_t)KCODES * KSPL];  // 1 MB
__device__ float g_cnorm[KCODES];
__device__ int   g_idx[NROWS];
__device__ int   g_flaglist[NROWS];
__device__ int   g_flagcount;
__device__ float g_partial[OUTBLK];

// ---------------- prep ----------------
__global__ void split_z_kernel(const float* __restrict__ z) {
    int e4 = blockIdx.x * blockDim.x + threadIdx.x;
    int base = e4 * 4;
    int row = base >> 8;
    int d   = base & 255;
    float4 v = *(const float4*)(z + base);
    float vv[4] = {v.x, v.y, v.z, v.w};
    __nv_bfloat16 h[4], l[4];
    #pragma unroll
    for (int i = 0; i < 4; i++) {
        h[i] = __float2bfloat16_rn(vv[i]);
        l[i] = __float2bfloat16_rn(vv[i] - __bfloat162float(h[i]));
    }
    __nv_bfloat162* ph = (__nv_bfloat162*)&g_zs[(size_t)row * KSPL + d];
    ph[0] = {h[0], h[1]}; ph[1] = {h[2], h[3]};
    __nv_bfloat162* pl = (__nv_bfloat162*)&g_zs[(size_t)row * KSPL + 256 + d];
    pl[0] = {l[0], l[1]}; pl[1] = {l[2], l[3]};
}

__global__ void split_w_kernel(const float* __restrict__ w) {
    if (blockIdx.x == 0 && threadIdx.x == 0) g_flagcount = 0;
    int e4 = blockIdx.x * blockDim.x + threadIdx.x;
    int base = e4 * 4;
    int row = base >> 8;
    int d   = base & 255;
    float4 v = *(const float4*)(w + base);
    float vv[4] = {v.x, v.y, v.z, v.w};
    __nv_bfloat16 h[4], l[4];
    #pragma unroll
    for (int i = 0; i < 4; i++) {
        h[i] = __float2bfloat16_rn(vv[i]);
        l[i] = __float2bfloat16_rn(vv[i] - __bfloat162float(h[i]));
    }
    __nv_bfloat162* ph = (__nv_bfloat162*)&g_ws[(size_t)row * KSPL + d];
    ph[0] = {h[0], h[1]}; ph[1] = {h[2], h[3]};
    __nv_bfloat162* pl = (__nv_bfloat162*)&g_ws[(size_t)row * KSPL + 256 + d];
    pl[0] = {l[0], l[1]}; pl[1] = {l[2], l[3]};
}

__global__ void cnorm_kernel(const float* __restrict__ w, int K) {
    int k = blockIdx.x * 8 + (threadIdx.x >> 5);
    int lane = threadIdx.x & 31;
    if (k >= K) return;
    const float4* wr = (const float4*)(w + (size_t)k * DDIM);
    float4 v0 = wr[lane];
    float4 v1 = wr[lane + 32];
    float s = v0.x*v0.x + v0.y*v0.y + v0.z*v0.z + v0.w*v0.w
            + v1.x*v1.x + v1.y*v1.y + v1.z*v1.z + v1.w*v1.w;
    #pragma unroll
    for (int m = 16; m; m >>= 1) s += __shfl_xor_sync(0xffffffffu, s, m);
    if (lane == 0) g_cnorm[k] = s;
}

// ---------------- GEMM helpers ----------------
__device__ __forceinline__ void cp16(unsigned saddr, const void* gaddr) {
    asm volatile("cp.async.cg.shared.global [%0], [%1], 16;\n" :: "r"(saddr), "l"(gaddr) : "memory");
}
__device__ __forceinline__ void cp_commit() { asm volatile("cp.async.commit_group;\n" ::: "memory"); }
template<int P> __device__ __forceinline__ void cp_wait() {
    asm volatile("cp.async.wait_group %0;\n" :: "n"(P) : "memory");
}
__device__ __forceinline__ void ldsm4(unsigned a, unsigned &r0, unsigned &r1, unsigned &r2, unsigned &r3) {
    asm volatile("ldmatrix.sync.aligned.m8n8.x4.shared.b16 {%0,%1,%2,%3}, [%4];"
                 : "=r"(r0), "=r"(r1), "=r"(r2), "=r"(r3) : "r"(a));
}
__device__ __forceinline__ void mma16816(float* c, const unsigned* a, const unsigned* b) {
    asm volatile("mma.sync.aligned.m16n8k16.row.col.f32.bf16.bf16.f32 "
                 "{%0,%1,%2,%3}, {%4,%5,%6,%7}, {%8,%9}, {%0,%1,%2,%3};"
                 : "+f"(c[0]), "+f"(c[1]), "+f"(c[2]), "+f"(c[3])
                 : "r"(a[0]), "r"(a[1]), "r"(a[2]), "r"(a[3]), "r"(b[0]), "r"(b[1]));
}
__device__ __forceinline__ bool lexless(float v, int i, float w, int j) {
    return v < w || (v == w && i < j);
}
__device__ __forceinline__ void top2_merge(float &v1, int &i1, float &v2, int &i2,
                                           float w1, int j1, float w2, int j2) {
    if (lexless(w1, j1, v1, i1)) {
        float nv2; int ni2;
        if (lexless(v1, i1, w2, j2)) { nv2 = v1; ni2 = i1; } else { nv2 = w2; ni2 = j2; }
        v1 = w1; i1 = j1; v2 = nv2; i2 = ni2;
    } else if (lexless(w1, j1, v2, i2)) {
        v2 = w1; i2 = j1;
    }
}

// load one BK=32 k-stage into smem buffers (packed-column remap)
__device__ __forceinline__ void load_stage(unsigned asmem, unsigned bsmem,
                                           int rowBase, int kc, int ks, int tid) {
    int kv = ks * BK;                        // virtual k in [0,768)
    int ca = (kv < 512) ? kv : kv - 512;     // A: [zh|zl|zh]
    int cb = (kv < 256) ? kv : kv - 256;     // B: [wh|wh|wl]
    #pragma unroll
    for (int it = 0; it < 2; it++) {
        int c = tid + it * 256;              // 512 chunks of 16B per operand
        int r = c >> 2, s = c & 3;
        cp16(asmem + (unsigned)((r * ASTRIDE + s * 8) * 2),
             &g_zs[(size_t)(rowBase + r) * KSPL + ca + s * 8]);
        cp16(bsmem + (unsigned)((r * ASTRIDE + s * 8) * 2),
             &g_ws[(size_t)(kc + r) * KSPL + cb + s * 8]);
    }
    cp_commit();
}

// ---------------- main GEMM + top2 (3-stage pipeline) ----------------
__global__ void __launch_bounds__(256, 2)
gemm_kernel(int N, int K)
{
    extern __shared__ __align__(16) __nv_bfloat16 dynsmem[];
    __nv_bfloat16* As = dynsmem;                       // [NSTAGE][BM*ASTRIDE]
    __nv_bfloat16* Bs = dynsmem + NSTAGE * BM * ASTRIDE;
    __shared__ float4 s_part[2][BM];
    __shared__ float4 s_run[BM];
    __shared__ float  s_cn[BN];

    const int tid  = threadIdx.x;
    const int lane = tid & 31;
    const int warp = tid >> 5;
    const int mw   = warp & 3;          // 4 m-warps
    const int nw   = warp >> 2;         // 2 n-warps
    const int wm0  = mw * 32;
    const int wn0  = nw * 64;
    const int rowBase = blockIdx.x * BM;

    unsigned asmem = (unsigned)__cvta_generic_to_shared(As);
    unsigned bsmem = (unsigned)__cvta_generic_to_shared(Bs);
    const unsigned TBYTES = BM * ASTRIDE * 2;   // bytes per stage per operand

    if (tid < BM) s_run[tid] = make_float4(INFV, __int_as_float(0x7fffffff),
                                           INFV, __int_as_float(0x7fffffff));

    const int KS = KVIRT / BK;          // 24

    for (int kc = 0; kc < K; kc += BN) {
        if (tid < BN) s_cn[tid] = g_cnorm[kc + tid];

        float acc[2][8][4];
        #pragma unroll
        for (int i = 0; i < 2; i++)
            #pragma unroll
            for (int j = 0; j < 8; j++)
                #pragma unroll
                for (int c = 0; c < 4; c++) acc[i][j][c] = 0.f;

        // prologue: stages 0,1
        load_stage(asmem, bsmem, rowBase, kc, 0, tid);
        load_stage(asmem + TBYTES, bsmem + TBYTES, rowBase, kc, 1, tid);

        for (int ks = 0; ks < KS; ks++) {
            int buf = ks % NSTAGE;
            if (ks == KS - 1) cp_wait<0>(); else cp_wait<1>();
            __syncthreads();            // stage ks ready; buf also safe for later rewrite
            if (ks + 2 < KS) {
                int nb = (ks + 2) % NSTAGE;
                load_stage(asmem + nb * TBYTES, bsmem + nb * TBYTES, rowBase, kc, ks + 2, tid);
            }

            unsigned abase = asmem + buf * TBYTES;
            unsigned bbase = bsmem + buf * TBYTES;
            #pragma unroll
            for (int kk = 0; kk < BK; kk += 16) {
                unsigned a[2][4];
                #pragma unroll
                for (int i = 0; i < 2; i++) {
                    int arow = wm0 + i * 16 + (lane & 15);
                    int acol = kk + ((lane >> 4) << 3);
                    ldsm4(abase + (unsigned)((arow * ASTRIDE + acol) * 2),
                          a[i][0], a[i][1], a[i][2], a[i][3]);
                }
                unsigned b[8][2];
                #pragma unroll
                for (int p = 0; p < 4; p++) {
                    int brow = wn0 + p * 16 + (lane & 7) + ((lane >> 4) << 3);
                    int bcol = kk + (((lane >> 3) & 1) << 3);
                    ldsm4(bbase + (unsigned)((brow * ASTRIDE + bcol) * 2),
                          b[2*p][0], b[2*p][1], b[2*p+1][0], b[2*p+1][1]);
                }
                #pragma unroll
                for (int i = 0; i < 2; i++)
                    #pragma unroll
                    for (int j = 0; j < 8; j++)
                        mma16816(acc[i][j], a[i], b[j]);
            }
        }
        __syncthreads();   // all reads of smem buffers done before next chunk's prologue

        // ---- epilogue: per-row top2 over this 128-code chunk ----
        #pragma unroll
        for (int i = 0; i < 2; i++) {
            #pragma unroll
            for (int h = 0; h < 2; h++) {
                float v1 = INFV; int i1 = 0x7fffffff;
                float v2 = INFV; int i2 = 0x7fffffff;
                #pragma unroll
                for (int j = 0; j < 8; j++) {
                    #pragma unroll
                    for (int c = 0; c < 2; c++) {
                        int col = wn0 + j * 8 + (lane & 3) * 2 + c;
                        float val = fmaf(-2.f, acc[i][j][h * 2 + c], s_cn[col]);
                        int idx = kc + col;
                        if (lexless(val, idx, v1, i1)) { v2 = v1; i2 = i1; v1 = val; i1 = idx; }
                        else if (lexless(val, idx, v2, i2)) { v2 = val; i2 = idx; }
                    }
                }
                #pragma unroll
                for (int off = 1; off < 4; off <<= 1) {
                    float ov1 = __shfl_xor_sync(0xffffffffu, v1, off);
                    int   oi1 = __shfl_xor_sync(0xffffffffu, i1, off);
                    float ov2 = __shfl_xor_sync(0xffffffffu, v2, off);
                    int   oi2 = __shfl_xor_sync(0xffffffffu, i2, off);
                    top2_merge(v1, i1, v2, i2, ov1, oi1, ov2, oi2);
                }
                if ((lane & 3) == 0) {
                    int r = wm0 + i * 16 + (lane >> 2) + h * 8;
                    s_part[nw][r] = make_float4(v1, __int_as_float(i1), v2, __int_as_float(i2));
                }
            }
        }
        __syncthreads();
        if (tid < BM) {
            float4 pa = s_part[0][tid];
            float4 pb = s_part[1][tid];
            float v1 = pa.x; int i1 = __float_as_int(pa.y);
            float v2 = pa.z; int i2 = __float_as_int(pa.w);
            top2_merge(v1, i1, v2, i2, pb.x, __float_as_int(pb.y), pb.z, __float_as_int(pb.w));
            float4 r = s_run[tid];
            float r1 = r.x; int ri1 = __float_as_int(r.y);
            float r2 = r.z; int ri2 = __float_as_int(r.w);
            top2_merge(r1, ri1, r2, ri2, v1, i1, v2, i2);
            s_run[tid] = make_float4(r1, __int_as_float(ri1), r2, __int_as_float(ri2));
        }
        __syncthreads();
    }

    if (tid < BM) {
        float4 r = s_run[tid];
        int row = rowBase + tid;
        g_idx[row] = __float_as_int(r.y);
        if (r.z - r.x <= MARGIN) {
            int pos = atomicAdd(&g_flagcount, 1);
            g_flaglist[pos] = row;
        }
    }
}

// ---------------- exact refine of flagged rows ----------------
#define RB 16
__global__ void refine_kernel(const float* __restrict__ z, const float* __restrict__ w, int K) {
    __shared__ float zrows[RB][260];
    __shared__ float wtile[RB][257];
    __shared__ int   rowids[RB];

    const int tid = threadIdx.x;
    const int rr  = tid >> 4;
    const int sub = tid & 15;
    const int fcount = g_flagcount;

    for (int base = blockIdx.x * RB; base < fcount; base += gridDim.x * RB) {
        int cnt = min(RB, fcount - base);
        if (tid < cnt) rowids[tid] = g_flaglist[base + tid];
        __syncthreads();
        for (int e = tid; e < cnt * 256; e += 256)
            zrows[e >> 8][e & 255] = z[(size_t)rowids[e >> 8] * DDIM + (e & 255)];

        float bv = INFV; int bi = 0x7fffffff;
        for (int cb = 0; cb < K; cb += RB) {
            __syncthreads();
            for (int e = tid; e < RB * 256; e += 256)
                wtile[e >> 8][e & 255] = w[(size_t)(cb + (e >> 8)) * DDIM + (e & 255)];
            __syncthreads();
            if (rr < cnt) {
                float dot = 0.f;
                #pragma unroll 8
                for (int d = 0; d < 256; d++)
                    dot = fmaf(zrows[rr][d], wtile[sub][d], dot);
                float val = fmaf(-2.f, dot, g_cnorm[cb + sub]);
                int code = cb + sub;
                if (lexless(val, code, bv, bi)) { bv = val; bi = code; }
            }
        }
        #pragma unroll
        for (int off = 8; off; off >>= 1) {
            float ov = __shfl_xor_sync(0xffffffffu, bv, off, 16);
            int   oi = __shfl_xor_sync(0xffffffffu, bi, off, 16);
            if (lexless(ov, oi, bv, bi)) { bv = ov; bi = oi; }
        }
        if (sub == 0 && rr < cnt) g_idx[rowids[rr]] = bi;
        __syncthreads();
    }
}

// ---------------- coalesced output assembly ----------------
__global__ void output_kernel(const float* __restrict__ z, const float* __restrict__ w,
                              float* __restrict__ out, int N)
{
    __shared__ int s_idx[OUTRPB];
    __shared__ float s_red[256];
    const int tid = threadIdx.x;
    const int base = blockIdx.x * OUTRPB;

    float* out_zq  = out + 1;
    float* out_idx = out + 1 + (size_t)N * DDIM;

    if (tid < OUTRPB) {
        int ix = g_idx[base + tid];
        s_idx[tid] = ix;
        out_idx[base + tid] = (float)ix;
    }
    __syncthreads();

    float lsum = 0.f;
    #pragma unroll 4
    for (int i = tid; i < OUTRPB * DDIM; i += 256) {
        int r = i >> 8, d = i & 255;
        float wv = w[(size_t)s_idx[r] * DDIM + d];
        float zv = z[(size_t)(base + r) * DDIM + d];
        float df = wv - zv;
        lsum += df * df;
        out_zq[(size_t)(base + r) * DDIM + d] = wv;
    }

    s_red[tid] = lsum;
    __syncthreads();
    #pragma unroll
    for (int m = 128; m; m >>= 1) {
        if (tid < m) s_red[tid] += s_red[tid + m];
        __syncthreads();
    }
    if (tid == 0) g_partial[blockIdx.x] = s_red[0];
}

__global__ void finalize_kernel(float* __restrict__ out, int nblocks, float scale) {
    __shared__ float s[512];
    int t = threadIdx.x;
    float v = 0.f;
    for (int i = t; i < nblocks; i += 512) v += g_partial[i];
    s[t] = v;
    __syncthreads();
    #pragma unroll
    for (int m = 256; m; m >>= 1) {
        if (t < m) s[t] += s[t + m];
        __syncthreads();
    }
    if (t == 0) out[0] = s[0] * scale;
}

extern "C" void kernel_launch(void* const* d_in, const int* in_sizes, int n_in,
                              void* d_out, int out_size) {
    const float* z = (const float*)d_in[0];
    const float* w = (const float*)d_in[1];
    float* out = (float*)d_out;

    int N = in_sizes[0] / DDIM;   // 65536
    int K = in_sizes[1] / DDIM;   // 1024

    const int dynsmem = NSTAGE * 2 * BM * ASTRIDE * 2;   // 61440 B
    cudaFuncSetAttribute(gemm_kernel, cudaFuncAttributeMaxDynamicSharedMemorySize, dynsmem);

    split_z_kernel<<<(N * DDIM) / 1024, 256>>>(z);
    split_w_kernel<<<(K * DDIM) / 1024, 256>>>(w);
    cnorm_kernel<<<(K + 7) / 8, 256>>>(w, K);
    gemm_kernel<<<N / BM, 256, dynsmem>>>(N, K);
    refine_kernel<<<64, 256>>>(z, w, K);
    output_kernel<<<N / OUTRPB, 256>>>(z, w, out, N);
    float scale = 0.25f / ((float)N * (float)DDIM);
    finalize_kernel<<<1, 512>>>(out, N / OUTRPB, scale);
}

// round 6
// speedup vs baseline: 2.1380x; 1.2905x over previous
#include <cuda_runtime.h>
#include <cuda_bf16.h>
#include <cstdint>

#define DDIM 256
#define NROWS 65536
#define KCODES 1024
#define KSPL 512                 // packed [hi(256) | lo(256)]
#define KVIRT 768                // virtual K: zh*wh + zl*wh + zh*wl
#define BM 128
#define BN 128
#define BK 64
#define ASTRIDE 72               // padded bf16 stride for BK=64 (conflict-free LDSM)
#define MARGIN 0.05f
#define INFV 3.4e38f
#define OUTRPB 16
#define OUTBLK (NROWS / OUTRPB)  // 4096
#define RGRID 256

__device__ __nv_bfloat16 g_zs[(size_t)NROWS * KSPL];   // 64 MB
__device__ __nv_bfloat16 g_ws[(size_t)KCODES * KSPL];  // 1 MB
__device__ float g_wt[DDIM * KCODES];                  // transposed codebook, 1 MB
__device__ float g_cnorm[KCODES];
__device__ int   g_idx[NROWS];
__device__ int   g_flaglist[NROWS];
__device__ int   g_flagcount;
__device__ float g_partial[OUTBLK];

// ---------------- prep ----------------
__global__ void split_z_kernel(const float* __restrict__ z) {
    int e4 = blockIdx.x * blockDim.x + threadIdx.x;
    int base = e4 * 4;
    int row = base >> 8;
    int d   = base & 255;
    float4 v = *(const float4*)(z + base);
    float vv[4] = {v.x, v.y, v.z, v.w};
    __nv_bfloat16 h[4], l[4];
    #pragma unroll
    for (int i = 0; i < 4; i++) {
        h[i] = __float2bfloat16_rn(vv[i]);
        l[i] = __float2bfloat16_rn(vv[i] - __bfloat162float(h[i]));
    }
    __nv_bfloat162* ph = (__nv_bfloat162*)&g_zs[(size_t)row * KSPL + d];
    ph[0] = {h[0], h[1]}; ph[1] = {h[2], h[3]};
    __nv_bfloat162* pl = (__nv_bfloat162*)&g_zs[(size_t)row * KSPL + 256 + d];
    pl[0] = {l[0], l[1]}; pl[1] = {l[2], l[3]};
}

__global__ void split_w_kernel(const float* __restrict__ w) {
    if (blockIdx.x == 0 && threadIdx.x == 0) g_flagcount = 0;
    int e4 = blockIdx.x * blockDim.x + threadIdx.x;
    int base = e4 * 4;
    int row = base >> 8;
    int d   = base & 255;
    float4 v = *(const float4*)(w + base);
    float vv[4] = {v.x, v.y, v.z, v.w};
    __nv_bfloat16 h[4], l[4];
    #pragma unroll
    for (int i = 0; i < 4; i++) {
        h[i] = __float2bfloat16_rn(vv[i]);
        l[i] = __float2bfloat16_rn(vv[i] - __bfloat162float(h[i]));
    }
    __nv_bfloat162* ph = (__nv_bfloat162*)&g_ws[(size_t)row * KSPL + d];
    ph[0] = {h[0], h[1]}; ph[1] = {h[2], h[3]};
    __nv_bfloat162* pl = (__nv_bfloat162*)&g_ws[(size_t)row * KSPL + 256 + d];
    pl[0] = {l[0], l[1]}; pl[1] = {l[2], l[3]};
}

__global__ void transpose_w_kernel(const float* __restrict__ w) {
    __shared__ float t[32][33];
    int kb = blockIdx.x * 32, db = blockIdx.y * 32;
    int tx = threadIdx.x, ty = threadIdx.y;   // 32 x 8
    #pragma unroll
    for (int i = 0; i < 4; i++)
        t[ty + i * 8][tx] = w[(size_t)(kb + ty + i * 8) * DDIM + db + tx];
    __syncthreads();
    #pragma unroll
    for (int i = 0; i < 4; i++)
        g_wt[(size_t)(db + ty + i * 8) * KCODES + kb + tx] = t[tx][ty + i * 8];
}

__global__ void cnorm_kernel(const float* __restrict__ w, int K) {
    int k = blockIdx.x * 8 + (threadIdx.x >> 5);
    int lane = threadIdx.x & 31;
    if (k >= K) return;
    const float4* wr = (const float4*)(w + (size_t)k * DDIM);
    float4 v0 = wr[lane];
    float4 v1 = wr[lane + 32];
    float s = v0.x*v0.x + v0.y*v0.y + v0.z*v0.z + v0.w*v0.w
            + v1.x*v1.x + v1.y*v1.y + v1.z*v1.z + v1.w*v1.w;
    #pragma unroll
    for (int m = 16; m; m >>= 1) s += __shfl_xor_sync(0xffffffffu, s, m);
    if (lane == 0) g_cnorm[k] = s;
}

// ---------------- GEMM helpers ----------------
__device__ __forceinline__ void cp16(unsigned saddr, const void* gaddr) {
    asm volatile("cp.async.cg.shared.global [%0], [%1], 16;\n" :: "r"(saddr), "l"(gaddr) : "memory");
}
__device__ __forceinline__ void cp_commit() { asm volatile("cp.async.commit_group;\n" ::: "memory"); }
template<int P> __device__ __forceinline__ void cp_wait() {
    asm volatile("cp.async.wait_group %0;\n" :: "n"(P) : "memory");
}
__device__ __forceinline__ void ldsm4(unsigned a, unsigned &r0, unsigned &r1, unsigned &r2, unsigned &r3) {
    asm volatile("ldmatrix.sync.aligned.m8n8.x4.shared.b16 {%0,%1,%2,%3}, [%4];"
                 : "=r"(r0), "=r"(r1), "=r"(r2), "=r"(r3) : "r"(a));
}
__device__ __forceinline__ void mma16816(float* c, const unsigned* a, const unsigned* b) {
    asm volatile("mma.sync.aligned.m16n8k16.row.col.f32.bf16.bf16.f32 "
                 "{%0,%1,%2,%3}, {%4,%5,%6,%7}, {%8,%9}, {%0,%1,%2,%3};"
                 : "+f"(c[0]), "+f"(c[1]), "+f"(c[2]), "+f"(c[3])
                 : "r"(a[0]), "r"(a[1]), "r"(a[2]), "r"(a[3]), "r"(b[0]), "r"(b[1]));
}
__device__ __forceinline__ bool lexless(float v, int i, float w, int j) {
    return v < w || (v == w && i < j);
}
__device__ __forceinline__ void top2_merge(float &v1, int &i1, float &v2, int &i2,
                                           float w1, int j1, float w2, int j2) {
    if (lexless(w1, j1, v1, i1)) {
        float nv2; int ni2;
        if (lexless(v1, i1, w2, j2)) { nv2 = v1; ni2 = i1; } else { nv2 = w2; ni2 = j2; }
        v1 = w1; i1 = j1; v2 = nv2; i2 = ni2;
    } else if (lexless(w1, j1, v2, i2)) {
        v2 = w1; i2 = j1;
    }
}

// load one BK=64 k-stage into smem buffers (packed-column remap)
__device__ __forceinline__ void load_stage(unsigned asmem, unsigned bsmem,
                                           int rowBase, int kc, int ks, int tid) {
    int kv = ks * BK;                        // virtual k in [0,768)
    int ca = (kv < 512) ? kv : kv - 512;     // A: [zh|zl|zh]
    int cb = (kv < 256) ? kv : kv - 256;     // B: [wh|wh|wl]
    #pragma unroll
    for (int it = 0; it < 4; it++) {
        int c = tid + it * 256;              // 1024 chunks of 16B per operand
        int r = c >> 3, s = c & 7;
        cp16(asmem + (unsigned)((r * ASTRIDE + s * 8) * 2),
             &g_zs[(size_t)(rowBase + r) * KSPL + ca + s * 8]);
        cp16(bsmem + (unsigned)((r * ASTRIDE + s * 8) * 2),
             &g_ws[(size_t)(kc + r) * KSPL + cb + s * 8]);
    }
    cp_commit();
}

// ---------------- main GEMM + top2 (BK=64, 2-stage pipeline) ----------------
__global__ void __launch_bounds__(256, 2)
gemm_kernel(int N, int K)
{
    extern __shared__ __align__(16) __nv_bfloat16 dynsmem[];
    __nv_bfloat16* As = dynsmem;                       // [2][BM*ASTRIDE]
    __nv_bfloat16* Bs = dynsmem + 2 * BM * ASTRIDE;
    __shared__ float4 s_part[2][BM];
    __shared__ float4 s_run[BM];
    __shared__ float  s_cn[BN];

    const int tid  = threadIdx.x;
    const int lane = tid & 31;
    const int warp = tid >> 5;
    const int mw   = warp & 3;          // 4 m-warps
    const int nw   = warp >> 2;         // 2 n-warps
    const int wm0  = mw * 32;
    const int wn0  = nw * 64;
    const int rowBase = blockIdx.x * BM;

    unsigned asmem = (unsigned)__cvta_generic_to_shared(As);
    unsigned bsmem = (unsigned)__cvta_generic_to_shared(Bs);
    const unsigned TBYTES = BM * ASTRIDE * 2;   // bytes per stage per operand

    if (tid < BM) s_run[tid] = make_float4(INFV, __int_as_float(0x7fffffff),
                                           INFV, __int_as_float(0x7fffffff));

    const int KS = KVIRT / BK;          // 12

    // global prologue: stage 0 of first chunk
    load_stage(asmem, bsmem, rowBase, 0, 0, tid);

    for (int kc = 0; kc < K; kc += BN) {
        if (tid < BN) s_cn[tid] = g_cnorm[kc + tid];

        float acc[2][8][4];
        #pragma unroll
        for (int i = 0; i < 2; i++)
            #pragma unroll
            for (int j = 0; j < 8; j++)
                #pragma unroll
                for (int c = 0; c < 4; c++) acc[i][j][c] = 0.f;

        for (int ks = 0; ks < KS; ks++) {
            int buf = ks & 1;
            cp_wait<0>();
            __syncthreads();            // stage ks data visible; other buf reads done
            if (ks + 1 < KS) {
                load_stage(asmem + (buf ^ 1) * TBYTES, bsmem + (buf ^ 1) * TBYTES,
                           rowBase, kc, ks + 1, tid);
            } else if (kc + BN < K) {   // prefetch next chunk's stage 0 under the epilogue
                load_stage(asmem + (buf ^ 1) * TBYTES, bsmem + (buf ^ 1) * TBYTES,
                           rowBase, kc + BN, 0, tid);
            }

            unsigned abase = asmem + buf * TBYTES;
            unsigned bbase = bsmem + buf * TBYTES;
            #pragma unroll
            for (int kk = 0; kk < BK; kk += 16) {
                unsigned a[2][4];
                #pragma unroll
                for (int i = 0; i < 2; i++) {
                    int arow = wm0 + i * 16 + (lane & 15);
                    int acol = kk + ((lane >> 4) << 3);
                    ldsm4(abase + (unsigned)((arow * ASTRIDE + acol) * 2),
                          a[i][0], a[i][1], a[i][2], a[i][3]);
                }
                unsigned b[8][2];
                #pragma unroll
                for (int p = 0; p < 4; p++) {
                    int brow = wn0 + p * 16 + (lane & 7) + ((lane >> 4) << 3);
                    int bcol = kk + (((lane >> 3) & 1) << 3);
                    ldsm4(bbase + (unsigned)((brow * ASTRIDE + bcol) * 2),
                          b[2*p][0], b[2*p][1], b[2*p+1][0], b[2*p+1][1]);
                }
                #pragma unroll
                for (int i = 0; i < 2; i++)
                    #pragma unroll
                    for (int j = 0; j < 8; j++)
                        mma16816(acc[i][j], a[i], b[j]);
            }
        }
        __syncthreads();   // all smem reads of the last stage done

        // ---- epilogue: per-row top2 over this 128-code chunk (cp.async for next kc in flight) ----
        #pragma unroll
        for (int i = 0; i < 2; i++) {
            #pragma unroll
            for (int h = 0; h < 2; h++) {
                float v1 = INFV; int i1 = 0x7fffffff;
                float v2 = INFV; int i2 = 0x7fffffff;
                #pragma unroll
                for (int j = 0; j < 8; j++) {
                    #pragma unroll
                    for (int c = 0; c < 2; c++) {
                        int col = wn0 + j * 8 + (lane & 3) * 2 + c;
                        float val = fmaf(-2.f, acc[i][j][h * 2 + c], s_cn[col]);
                        int idx = kc + col;
                        if (lexless(val, idx, v1, i1)) { v2 = v1; i2 = i1; v1 = val; i1 = idx; }
                        else if (lexless(val, idx, v2, i2)) { v2 = val; i2 = idx; }
                    }
                }
                #pragma unroll
                for (int off = 1; off < 4; off <<= 1) {
                    float ov1 = __shfl_xor_sync(0xffffffffu, v1, off);
                    int   oi1 = __shfl_xor_sync(0xffffffffu, i1, off);
                    float ov2 = __shfl_xor_sync(0xffffffffu, v2, off);
                    int   oi2 = __shfl_xor_sync(0xffffffffu, i2, off);
                    top2_merge(v1, i1, v2, i2, ov1, oi1, ov2, oi2);
                }
                if ((lane & 3) == 0) {
                    int r = wm0 + i * 16 + (lane >> 2) + h * 8;
                    s_part[nw][r] = make_float4(v1, __int_as_float(i1), v2, __int_as_float(i2));
                }
            }
        }
        __syncthreads();
        if (tid < BM) {
            float4 pa = s_part[0][tid];
            float4 pb = s_part[1][tid];
            float v1 = pa.x; int i1 = __float_as_int(pa.y);
            float v2 = pa.z; int i2 = __float_as_int(pa.w);
            top2_merge(v1, i1, v2, i2, pb.x, __float_as_int(pb.y), pb.z, __float_as_int(pb.w));
            float4 r = s_run[tid];
            float r1 = r.x; int ri1 = __float_as_int(r.y);
            float r2 = r.z; int ri2 = __float_as_int(r.w);
            top2_merge(r1, ri1, r2, ri2, v1, i1, v2, i2);
            s_run[tid] = make_float4(r1, __int_as_float(ri1), r2, __int_as_float(ri2));
        }
        __syncthreads();
    }

    if (tid < BM) {
        float4 r = s_run[tid];
        int row = rowBase + tid;
        g_idx[row] = __float_as_int(r.y);
        if (r.z - r.x <= MARGIN) {
            int pos = atomicAdd(&g_flagcount, 1);
            g_flaglist[pos] = row;
        }
    }
}

// ---------------- exact refine of flagged rows (wT-based, FMA-bound) ----------------
__global__ void refine_kernel(const float* __restrict__ z, int K) {
    __shared__ __align__(16) float zs[8][260];
    __shared__ int   rowids[8];
    __shared__ float sbv[8][8];
    __shared__ int   sbi[8][8];

    const int tid  = threadIdx.x;
    const int lane = tid & 31;
    const int warp = tid >> 5;
    const int fcount = g_flagcount;

    for (int base = blockIdx.x * 8; base < fcount; base += gridDim.x * 8) {
        int cnt = min(8, fcount - base);
        if (tid < cnt) rowids[tid] = g_flaglist[base + tid];
        __syncthreads();
        for (int e = tid; e < cnt * 256; e += 256)
            zs[e >> 8][e & 255] = z[(size_t)rowids[e >> 8] * DDIM + (e & 255)];
        __syncthreads();

        float bv[8]; int bi[8];
        #pragma unroll
        for (int r = 0; r < 8; r++) { bv[r] = INFV; bi[r] = 0x7fffffff; }

        #pragma unroll 1
        for (int p = 0; p < 4; p++) {
            int k = p * 256 + tid;             // this thread's code column
            float acc[8];
            #pragma unroll
            for (int r = 0; r < 8; r++) acc[r] = 0.f;
            #pragma unroll 4
            for (int d4 = 0; d4 < 64; d4++) {
                float w0 = g_wt[(size_t)(d4 * 4 + 0) * KCODES + k];
                float w1 = g_wt[(size_t)(d4 * 4 + 1) * KCODES + k];
                float w2 = g_wt[(size_t)(d4 * 4 + 2) * KCODES + k];
                float w3 = g_wt[(size_t)(d4 * 4 + 3) * KCODES + k];
                #pragma unroll
                for (int r = 0; r < 8; r++) {
                    float4 zv = *(const float4*)&zs[r][d4 * 4];
                    acc[r] = fmaf(zv.x, w0, acc[r]);
                    acc[r] = fmaf(zv.y, w1, acc[r]);
                    acc[r] = fmaf(zv.z, w2, acc[r]);
                    acc[r] = fmaf(zv.w, w3, acc[r]);
                }
            }
            float cn = g_cnorm[k];
            #pragma unroll
            for (int r = 0; r < 8; r++) {
                float val = fmaf(-2.f, acc[r], cn);
                if (lexless(val, k, bv[r], bi[r])) { bv[r] = val; bi[r] = k; }
            }
        }

        #pragma unroll
        for (int r = 0; r < 8; r++) {
            float v = bv[r]; int i = bi[r];
            #pragma unroll
            for (int off = 16; off; off >>= 1) {
                float ov = __shfl_xor_sync(0xffffffffu, v, off);
                int   oi = __shfl_xor_sync(0xffffffffu, i, off);
                if (lexless(ov, oi, v, i)) { v = ov; i = oi; }
            }
            if (lane == 0) { sbv[warp][r] = v; sbi[warp][r] = i; }
        }
        __syncthreads();
        if (tid < cnt) {
            float v = sbv[0][tid]; int i = sbi[0][tid];
            #pragma unroll
            for (int wq = 1; wq < 8; wq++)
                if (lexless(sbv[wq][tid], sbi[wq][tid], v, i)) { v = sbv[wq][tid]; i = sbi[wq][tid]; }
            g_idx[rowids[tid]] = i;
        }
        __syncthreads();
    }
}

// ---------------- coalesced output assembly ----------------
__global__ void output_kernel(const float* __restrict__ z, const float* __restrict__ w,
                              float* __restrict__ out, int N)
{
    __shared__ int s_idx[OUTRPB];
    __shared__ float s_red[256];
    const int tid = threadIdx.x;
    const int base = blockIdx.x * OUTRPB;

    float* out_zq  = out + 1;
    float* out_idx = out + 1 + (size_t)N * DDIM;

    if (tid < OUTRPB) {
        int ix = g_idx[base + tid];
        s_idx[tid] = ix;
        out_idx[base + tid] = (float)ix;
    }
    __syncthreads();

    float lsum = 0.f;
    #pragma unroll 4
    for (int i = tid; i < OUTRPB * DDIM; i += 256) {
        int r = i >> 8, d = i & 255;
        float wv = w[(size_t)s_idx[r] * DDIM + d];
        float zv = z[(size_t)(base + r) * DDIM + d];
        float df = wv - zv;
        lsum += df * df;
        out_zq[(size_t)(base + r) * DDIM + d] = wv;
    }

    s_red[tid] = lsum;
    __syncthreads();
    #pragma unroll
    for (int m = 128; m; m >>= 1) {
        if (tid < m) s_red[tid] += s_red[tid + m];
        __syncthreads();
    }
    if (tid == 0) g_partial[blockIdx.x] = s_red[0];
}

__global__ void finalize_kernel(float* __restrict__ out, int nblocks, float scale) {
    __shared__ float s[512];
    int t = threadIdx.x;
    float v = 0.f;
    for (int i = t; i < nblocks; i += 512) v += g_partial[i];
    s[t] = v;
    __syncthreads();
    #pragma unroll
    for (int m = 256; m; m >>= 1) {
        if (t < m) s[t] += s[t + m];
        __syncthreads();
    }
    if (t == 0) out[0] = s[0] * scale;
}

extern "C" void kernel_launch(void* const* d_in, const int* in_sizes, int n_in,
                              void* d_out, int out_size) {
    const float* z = (const float*)d_in[0];
    const float* w = (const float*)d_in[1];
    float* out = (float*)d_out;

    int N = in_sizes[0] / DDIM;   // 65536
    int K = in_sizes[1] / DDIM;   // 1024

    const int dynsmem = 2 * 2 * BM * ASTRIDE * 2;   // 73728 B
    cudaFuncSetAttribute(gemm_kernel, cudaFuncAttributeMaxDynamicSharedMemorySize, dynsmem);

    split_z_kernel<<<(N * DDIM) / 1024, 256>>>(z);
    split_w_kernel<<<(K * DDIM) / 1024, 256>>>(w);
    transpose_w_kernel<<<dim3(K / 32, DDIM / 32), dim3(32, 8)>>>(w);
    cnorm_kernel<<<(K + 7) / 8, 256>>>(w, K);
    gemm_kernel<<<N / BM, 256, dynsmem>>>(N, K);
    refine_kernel<<<RGRID, 256>>>(z, K);
    output_kernel<<<N / OUTRPB, 256>>>(z, w, out, N);
    float scale = 0.25f / ((float)N * (float)DDIM);
    finalize_kernel<<<1, 512>>>(out, N / OUTRPB, scale);
}